// round 2
// baseline (speedup 1.0000x reference)
#include <cuda_runtime.h>
#include <math.h>

#define Bsz 2048
#define Tt  512
#define Vv  64
#define Hh  256
#define HV  320   // H + V
#define BM  16    // batch rows per block

// Scratch (device globals; no allocation allowed in kernel_launch)
__device__ __align__(16) float g_thetaT4[HV * Hh];   // packed [k/4][h][4]
__device__ __align__(16) float g_stateA[Bsz * Hh];
__device__ __align__(16) float g_stateB[Bsz * Hh];

// theta [H, H+V] row-major  ->  packed layout: g_thetaT4[(k>>2)*(H*4) + h*4 + (k&3)]
__global__ void transpose_kernel(const float* __restrict__ theta) {
    int idx = blockIdx.x * blockDim.x + threadIdx.x;
    if (idx >= HV * Hh) return;
    int k = idx >> 8;      // 0..319
    int h = idx & 255;     // 0..255
    g_thetaT4[(k >> 2) * (Hh * 4) + h * 4 + (k & 3)] = theta[h * HV + k];
}

// One recurrence step: z = [state, token] @ theta^T + bias; layernorm(ddof=1); relu
__global__ __launch_bounds__(256) void step_kernel(
    const float* __restrict__ sf,     // [B, T, V]
    const float* __restrict__ bias,   // [1]
    int t, int first, int parity)
{
    __shared__ __align__(16) float st_s[BM][HV];   // 20 KB
    __shared__ float mean_s[BM];
    __shared__ float rstd_s[BM];

    const float* state_in  = parity ? g_stateB : g_stateA;
    float*       state_out = parity ? g_stateA : g_stateB;

    const int tid = threadIdx.x;
    const int b0  = blockIdx.x * BM;

    // ---- load st tile into shared ----
    if (first) {
        for (int idx = tid; idx < BM * Hh; idx += 256)
            st_s[idx >> 8][idx & 255] = 0.0f;
    } else {
        for (int idx = tid; idx < BM * Hh; idx += 256) {
            int m = idx >> 8, k = idx & 255;
            st_s[m][k] = state_in[(b0 + m) * Hh + k];
        }
    }
    for (int idx = tid; idx < BM * Vv; idx += 256) {
        int m = idx >> 6, v = idx & 63;
        st_s[m][Hh + v] = sf[((size_t)(b0 + m) * Tt + t) * Vv + v];
    }
    __syncthreads();

    // ---- GEMM: each thread computes column h for BM rows ----
    const float bval = bias[0];
    float acc[BM];
#pragma unroll
    for (int m = 0; m < BM; m++) acc[m] = bval;

    const int h = tid;
    const float4* th = reinterpret_cast<const float4*>(g_thetaT4) + h;

#pragma unroll 2
    for (int c = 0; c < HV / 4; c++) {
        float4 tv = th[c * Hh];           // 1 coalesced LDG.128 per chunk
        int k0 = c * 4;
#pragma unroll
        for (int m = 0; m < BM; m++) {
            float4 s = *reinterpret_cast<const float4*>(&st_s[m][k0]); // broadcast LDS.128
            acc[m] = fmaf(s.x, tv.x, acc[m]);
            acc[m] = fmaf(s.y, tv.y, acc[m]);
            acc[m] = fmaf(s.z, tv.z, acc[m]);
            acc[m] = fmaf(s.w, tv.w, acc[m]);
        }
    }

    // ---- layernorm (mean, std with Bessel correction) ----
    __syncthreads();                       // all st_s reads done; reuse as z buffer
    float* z = &st_s[0][0];                // [BM][Hh] = 16 KB, fits in 20 KB
#pragma unroll
    for (int m = 0; m < BM; m++) z[m * Hh + h] = acc[m];
    __syncthreads();

    const int wid = tid >> 5, lane = tid & 31;
    for (int m = wid; m < BM; m += 8) {
        float s = 0.0f, ss = 0.0f;
#pragma unroll
        for (int j = 0; j < Hh / 32; j++) {
            float v = z[m * Hh + j * 32 + lane];
            s += v;
            ss = fmaf(v, v, ss);
        }
#pragma unroll
        for (int off = 16; off; off >>= 1) {
            s  += __shfl_xor_sync(0xffffffffu, s, off);
            ss += __shfl_xor_sync(0xffffffffu, ss, off);
        }
        if (lane == 0) {
            float mean = s * (1.0f / Hh);
            float var  = (ss - (float)Hh * mean * mean) * (1.0f / (Hh - 1));
            var = fmaxf(var, 1e-30f);
            float r = rsqrtf(var);
            r = r * (1.5f - 0.5f * var * r * r);   // Newton refinement
            mean_s[m] = mean;
            rstd_s[m] = r;
        }
    }
    __syncthreads();

#pragma unroll
    for (int m = 0; m < BM; m++) {
        float o = (acc[m] - mean_s[m]) * rstd_s[m];
        state_out[(b0 + m) * Hh + h] = fmaxf(o, 0.0f);
    }
}

// logits[b] = sigmoid(sum_h state[b,h] * theta_dot[h])
__global__ void logits_kernel(const float* __restrict__ theta_dot, float* __restrict__ out) {
    const float* state = g_stateA;   // final state lives in A after 512 steps
    int wid = threadIdx.x >> 5, lane = threadIdx.x & 31;
    int row = blockIdx.x * 8 + wid;
    float s = 0.0f;
#pragma unroll
    for (int j = 0; j < Hh / 32; j++) {
        int hh = j * 32 + lane;
        s = fmaf(state[row * Hh + hh], theta_dot[hh], s);
    }
#pragma unroll
    for (int off = 16; off; off >>= 1)
        s += __shfl_xor_sync(0xffffffffu, s, off);
    if (lane == 0) out[row] = 1.0f / (1.0f + expf(-s));
}

extern "C" void kernel_launch(void* const* d_in, const int* in_sizes, int n_in,
                              void* d_out, int out_size) {
    const float* sf        = (const float*)d_in[0];
    const float* theta     = (const float*)d_in[1];
    const float* bias      = (const float*)d_in[2];
    const float* theta_dot = (const float*)d_in[3];
    float*       out       = (float*)d_out;

    transpose_kernel<<<HV, 256>>>(theta);

    for (int t = 0; t < Tt; t++) {
        // parity: t even -> read A write B ; t odd -> read B write A
        step_kernel<<<Bsz / BM, 256>>>(sf, bias, t, (t == 0) ? 1 : 0, t & 1);
    }

    logits_kernel<<<Bsz / 8, 256>>>(theta_dot, out);
}

// round 3
// speedup vs baseline: 1.9339x; 1.9339x over previous
#include <cuda_runtime.h>
#include <math.h>

#define Bsz 2048
#define Tt  512
#define Vv  64
#define Hh  256
#define HV  320          // H + V
#define BM  16           // batch rows per block
#define BMP 20           // padded row width (floats) -> 16B-aligned rows, reduced bank conflicts
#define NBLK (Bsz / BM)  // 128 blocks

// theta packed: g_thetaT4[(k>>2)*(Hh*4) + h*4 + (k&3)]
__device__ __align__(16) float g_thetaT4[HV * Hh];

// ---------- packed f32x2 helpers ----------
__device__ __forceinline__ unsigned long long fma2(unsigned long long a,
                                                   unsigned long long b,
                                                   unsigned long long c) {
    unsigned long long d;
    asm("fma.rn.f32x2 %0, %1, %2, %3;" : "=l"(d) : "l"(a), "l"(b), "l"(c));
    return d;
}
__device__ __forceinline__ unsigned long long pack2(float x) {
    unsigned long long d;
    asm("mov.b64 %0, {%1, %1};" : "=l"(d) : "r"(__float_as_uint(x)));
    return d;
}
__device__ __forceinline__ void unpack2(unsigned long long v, float& lo, float& hi) {
    unsigned int a, b;
    asm("mov.b64 {%0, %1}, %2;" : "=r"(a), "=r"(b) : "l"(v));
    lo = __uint_as_float(a);
    hi = __uint_as_float(b);
}

// theta [H, H+V] row-major -> packed chunk layout
__global__ void transpose_kernel(const float* __restrict__ theta) {
    int idx = blockIdx.x * blockDim.x + threadIdx.x;
    if (idx >= HV * Hh) return;
    int k = idx >> 8;
    int h = idx & 255;
    g_thetaT4[(k >> 2) * (Hh * 4) + h * 4 + (k & 3)] = theta[h * HV + k];
}

// Persistent kernel: each block owns BM batch rows for ALL T steps.
__global__ void __launch_bounds__(256, 1) rnn_persistent(
    const float* __restrict__ sf,        // [B, T, V]
    const float* __restrict__ bias_g,    // [1]
    const float* __restrict__ theta_dot, // [1, H]
    float* __restrict__ out)             // [B]
{
    __shared__ __align__(16) float st_p[HV][BMP];   // state+token, k-major: 25.6 KB
    __shared__ __align__(16) float z_s[BM][Hh];     // z scratch for LN reduce: 16 KB
    __shared__ float mean_s[BM];
    __shared__ float rstd_s[BM];

    const int tid = threadIdx.x;
    const int h   = tid;                 // one hidden column per thread
    const int wid = tid >> 5, lane = tid & 31;
    const int b0  = blockIdx.x * BM;

    // token-load mapping: thread -> (row m_t, 4-float group v4)
    const int m_t = tid >> 4;            // 0..15
    const int v4  = tid & 15;            // 0..15  (v = v4*4 .. v4*4+3)

    const float bval = bias_g[0];

    // ---- zero initial state rows (k = 0..255) ----
    for (int idx = tid; idx < Hh * BMP; idx += 256)
        (&st_p[0][0])[idx] = 0.0f;

    // ---- preload tokens for t=0 into shared ----
    {
        float4 tk = *reinterpret_cast<const float4*>(
            &sf[((size_t)(b0 + m_t) * Tt + 0) * Vv + v4 * 4]);
        st_p[Hh + v4 * 4 + 0][m_t] = tk.x;
        st_p[Hh + v4 * 4 + 1][m_t] = tk.y;
        st_p[Hh + v4 * 4 + 2][m_t] = tk.z;
        st_p[Hh + v4 * 4 + 3][m_t] = tk.w;
    }

    const float4* th = reinterpret_cast<const float4*>(g_thetaT4) + h;

    float zr[BM];   // this thread's z / state values for its column, all BM rows

    for (int t = 0; t < Tt; t++) {
        __syncthreads();   // (d) state writes + token STS from prev iter visible

        // prefetch next step's token straight away (overlaps with GEMM)
        float4 tok;
        const bool havet = (t + 1 < Tt);
        if (havet) {
            tok = *reinterpret_cast<const float4*>(
                &sf[((size_t)(b0 + m_t) * Tt + (t + 1)) * Vv + v4 * 4]);
        }

        // ---------- GEMM: z[h, m(0..15)] packed as 8 f32x2 accumulators ----------
        unsigned long long acc[8];
#pragma unroll
        for (int j = 0; j < 8; j++) acc[j] = pack2(bval);

        float4 tv = th[0];
#pragma unroll 4
        for (int c = 0; c < HV / 4; c++) {
            float4 tn = th[((c + 1 < HV / 4) ? c + 1 : c) * Hh];  // prefetch next chunk
            float tva[4];
            *reinterpret_cast<float4*>(tva) = tv;
#pragma unroll
            for (int kk = 0; kk < 4; kk++) {
                unsigned long long tk = pack2(tva[kk]);
                const ulonglong2* sp =
                    reinterpret_cast<const ulonglong2*>(&st_p[c * 4 + kk][0]);
                ulonglong2 p0 = sp[0];   // rows 0..3
                ulonglong2 p1 = sp[1];   // rows 4..7
                ulonglong2 p2 = sp[2];   // rows 8..11
                ulonglong2 p3 = sp[3];   // rows 12..15
                acc[0] = fma2(p0.x, tk, acc[0]);
                acc[1] = fma2(p0.y, tk, acc[1]);
                acc[2] = fma2(p1.x, tk, acc[2]);
                acc[3] = fma2(p1.y, tk, acc[3]);
                acc[4] = fma2(p2.x, tk, acc[4]);
                acc[5] = fma2(p2.y, tk, acc[5]);
                acc[6] = fma2(p3.x, tk, acc[6]);
                acc[7] = fma2(p3.y, tk, acc[7]);
            }
            tv = tn;
        }

        // unpack z and stage for the per-row reduction
#pragma unroll
        for (int j = 0; j < 8; j++) unpack2(acc[j], zr[2 * j], zr[2 * j + 1]);
#pragma unroll
        for (int m = 0; m < BM; m++) z_s[m][h] = zr[m];

        __syncthreads();   // (b) all GEMM reads done; z_s populated

        // ---------- per-row mean / Bessel std (8 warps x 2 rows) ----------
        for (int m = wid; m < BM; m += 8) {
            float s = 0.0f, ss = 0.0f;
#pragma unroll
            for (int j = 0; j < Hh / 32; j++) {
                float v = z_s[m][j * 32 + lane];
                s += v;
                ss = fmaf(v, v, ss);
            }
#pragma unroll
            for (int off = 16; off; off >>= 1) {
                s  += __shfl_xor_sync(0xffffffffu, s, off);
                ss += __shfl_xor_sync(0xffffffffu, ss, off);
            }
            if (lane == 0) {
                float mean = s * (1.0f / Hh);
                float var  = (ss - (float)Hh * mean * mean) * (1.0f / (Hh - 1));
                var = fmaxf(var, 1e-30f);
                float r = rsqrtf(var);
                r = r * (1.5f - 0.5f * var * r * r);   // Newton refine
                mean_s[m] = mean;
                rstd_s[m] = r;
            }
        }

        // stage next step's tokens into shared (safe: GEMM reads finished at (b))
        if (havet) {
            st_p[Hh + v4 * 4 + 0][m_t] = tok.x;
            st_p[Hh + v4 * 4 + 1][m_t] = tok.y;
            st_p[Hh + v4 * 4 + 2][m_t] = tok.z;
            st_p[Hh + v4 * 4 + 3][m_t] = tok.w;
        }

        __syncthreads();   // (c) mean/rstd ready

        // ---------- layernorm apply + relu, write state back into shared ----------
#pragma unroll
        for (int m = 0; m < BM; m++) {
            float v = fmaxf((zr[m] - mean_s[m]) * rstd_s[m], 0.0f);
            zr[m] = v;
            st_p[h][m] = v;
        }
    }

    // ---------- logits: out[b] = sigmoid(sum_h state[b,h] * theta_dot[h]) ----------
    const float td = theta_dot[h];
#pragma unroll
    for (int m = 0; m < BM; m++) z_s[m][h] = zr[m] * td;
    __syncthreads();

    for (int m = wid; m < BM; m += 8) {
        float s = 0.0f;
#pragma unroll
        for (int j = 0; j < Hh / 32; j++) s += z_s[m][j * 32 + lane];
#pragma unroll
        for (int off = 16; off; off >>= 1)
            s += __shfl_xor_sync(0xffffffffu, s, off);
        if (lane == 0) out[b0 + m] = 1.0f / (1.0f + expf(-s));
    }
}

extern "C" void kernel_launch(void* const* d_in, const int* in_sizes, int n_in,
                              void* d_out, int out_size) {
    const float* sf        = (const float*)d_in[0];
    const float* theta     = (const float*)d_in[1];
    const float* bias      = (const float*)d_in[2];
    const float* theta_dot = (const float*)d_in[3];
    float*       out       = (float*)d_out;

    transpose_kernel<<<HV, 256>>>(theta);
    rnn_persistent<<<NBLK, 256>>>(sf, bias, theta_dot, out);
}

// round 4
// speedup vs baseline: 1.9348x; 1.0005x over previous
#include <cuda_runtime.h>
#include <math.h>

#define Bsz 2048
#define Tt  512
#define Vv  64
#define Hh  256
#define HV  320          // H + V
#define BM  16           // batch rows per block
#define BMP 20           // padded row width (floats) -> 16B-aligned rows, reduced bank conflicts
#define NBLK (Bsz / BM)  // 128 blocks

// theta packed: g_thetaT4[(k>>2)*(Hh*4) + h*4 + (k&3)]
__device__ __align__(16) float g_thetaT4[HV * Hh];

// ---------- packed f32x2 helpers ----------
__device__ __forceinline__ unsigned long long fma2(unsigned long long a,
                                                   unsigned long long b,
                                                   unsigned long long c) {
    unsigned long long d;
    asm("fma.rn.f32x2 %0, %1, %2, %3;" : "=l"(d) : "l"(a), "l"(b), "l"(c));
    return d;
}
__device__ __forceinline__ unsigned long long pack2(float x) {
    unsigned long long d;
    asm("mov.b64 %0, {%1, %1};" : "=l"(d) : "r"(__float_as_uint(x)));
    return d;
}
__device__ __forceinline__ void unpack2(unsigned long long v, float& lo, float& hi) {
    unsigned int a, b;
    asm("mov.b64 {%0, %1}, %2;" : "=r"(a), "=r"(b) : "l"(v));
    lo = __uint_as_float(a);
    hi = __uint_as_float(b);
}

// theta [H, H+V] row-major -> packed chunk layout
__global__ void transpose_kernel(const float* __restrict__ theta) {
    int idx = blockIdx.x * blockDim.x + threadIdx.x;
    if (idx >= HV * Hh) return;
    int k = idx >> 8;
    int h = idx & 255;
    g_thetaT4[(k >> 2) * (Hh * 4) + h * 4 + (k & 3)] = theta[h * HV + k];
}

// Persistent kernel: each block owns BM batch rows for ALL T steps.
__global__ void __launch_bounds__(256, 1) rnn_persistent(
    const float* __restrict__ sf,        // [B, T, V]
    const float* __restrict__ bias_g,    // [1]
    const float* __restrict__ theta_dot, // [1, H]
    float* __restrict__ out)             // [B]
{
    __shared__ __align__(16) float st_p[HV][BMP];   // state+token, k-major: 25.6 KB
    __shared__ __align__(16) float z_s[BM][Hh];     // z scratch for LN reduce: 16 KB
    __shared__ float mean_s[BM];
    __shared__ float rstd_s[BM];

    const int tid = threadIdx.x;
    const int h   = tid;                 // one hidden column per thread
    const int wid = tid >> 5, lane = tid & 31;
    const int b0  = blockIdx.x * BM;

    // token-load mapping: thread -> (row m_t, 4-float group v4)
    const int m_t = tid >> 4;            // 0..15
    const int v4  = tid & 15;            // 0..15  (v = v4*4 .. v4*4+3)

    const float bval = bias_g[0];

    // ---- zero initial state rows (k = 0..255) ----
    for (int idx = tid; idx < Hh * BMP; idx += 256)
        (&st_p[0][0])[idx] = 0.0f;

    // ---- preload tokens for t=0 into shared ----
    {
        float4 tk = *reinterpret_cast<const float4*>(
            &sf[((size_t)(b0 + m_t) * Tt + 0) * Vv + v4 * 4]);
        st_p[Hh + v4 * 4 + 0][m_t] = tk.x;
        st_p[Hh + v4 * 4 + 1][m_t] = tk.y;
        st_p[Hh + v4 * 4 + 2][m_t] = tk.z;
        st_p[Hh + v4 * 4 + 3][m_t] = tk.w;
    }

    const float4* th = reinterpret_cast<const float4*>(g_thetaT4) + h;

    float zr[BM];   // this thread's z / state values for its column, all BM rows

    for (int t = 0; t < Tt; t++) {
        __syncthreads();   // (d) state writes + token STS from prev iter visible

        // prefetch next step's token straight away (overlaps with GEMM)
        float4 tok;
        const bool havet = (t + 1 < Tt);
        if (havet) {
            tok = *reinterpret_cast<const float4*>(
                &sf[((size_t)(b0 + m_t) * Tt + (t + 1)) * Vv + v4 * 4]);
        }

        // ---------- GEMM: z[h, m(0..15)] packed as 8 f32x2 accumulators ----------
        unsigned long long acc[8];
#pragma unroll
        for (int j = 0; j < 8; j++) acc[j] = pack2(bval);

        float4 tv = th[0];
#pragma unroll 4
        for (int c = 0; c < HV / 4; c++) {
            float4 tn = th[((c + 1 < HV / 4) ? c + 1 : c) * Hh];  // prefetch next chunk
            float tva[4];
            *reinterpret_cast<float4*>(tva) = tv;
#pragma unroll
            for (int kk = 0; kk < 4; kk++) {
                unsigned long long tk = pack2(tva[kk]);
                const ulonglong2* sp =
                    reinterpret_cast<const ulonglong2*>(&st_p[c * 4 + kk][0]);
                ulonglong2 p0 = sp[0];   // rows 0..3
                ulonglong2 p1 = sp[1];   // rows 4..7
                ulonglong2 p2 = sp[2];   // rows 8..11
                ulonglong2 p3 = sp[3];   // rows 12..15
                acc[0] = fma2(p0.x, tk, acc[0]);
                acc[1] = fma2(p0.y, tk, acc[1]);
                acc[2] = fma2(p1.x, tk, acc[2]);
                acc[3] = fma2(p1.y, tk, acc[3]);
                acc[4] = fma2(p2.x, tk, acc[4]);
                acc[5] = fma2(p2.y, tk, acc[5]);
                acc[6] = fma2(p3.x, tk, acc[6]);
                acc[7] = fma2(p3.y, tk, acc[7]);
            }
            tv = tn;
        }

        // unpack z and stage for the per-row reduction
#pragma unroll
        for (int j = 0; j < 8; j++) unpack2(acc[j], zr[2 * j], zr[2 * j + 1]);
#pragma unroll
        for (int m = 0; m < BM; m++) z_s[m][h] = zr[m];

        __syncthreads();   // (b) all GEMM reads done; z_s populated

        // ---------- per-row mean / Bessel std (8 warps x 2 rows) ----------
        for (int m = wid; m < BM; m += 8) {
            float s = 0.0f, ss = 0.0f;
#pragma unroll
            for (int j = 0; j < Hh / 32; j++) {
                float v = z_s[m][j * 32 + lane];
                s += v;
                ss = fmaf(v, v, ss);
            }
#pragma unroll
            for (int off = 16; off; off >>= 1) {
                s  += __shfl_xor_sync(0xffffffffu, s, off);
                ss += __shfl_xor_sync(0xffffffffu, ss, off);
            }
            if (lane == 0) {
                float mean = s * (1.0f / Hh);
                float var  = (ss - (float)Hh * mean * mean) * (1.0f / (Hh - 1));
                var = fmaxf(var, 1e-30f);
                float r = rsqrtf(var);
                r = r * (1.5f - 0.5f * var * r * r);   // Newton refine
                mean_s[m] = mean;
                rstd_s[m] = r;
            }
        }

        // stage next step's tokens into shared (safe: GEMM reads finished at (b))
        if (havet) {
            st_p[Hh + v4 * 4 + 0][m_t] = tok.x;
            st_p[Hh + v4 * 4 + 1][m_t] = tok.y;
            st_p[Hh + v4 * 4 + 2][m_t] = tok.z;
            st_p[Hh + v4 * 4 + 3][m_t] = tok.w;
        }

        __syncthreads();   // (c) mean/rstd ready

        // ---------- layernorm apply + relu, write state back into shared ----------
#pragma unroll
        for (int m = 0; m < BM; m++) {
            float v = fmaxf((zr[m] - mean_s[m]) * rstd_s[m], 0.0f);
            zr[m] = v;
            st_p[h][m] = v;
        }
    }

    // ---------- logits: out[b] = sigmoid(sum_h state[b,h] * theta_dot[h]) ----------
    const float td = theta_dot[h];
#pragma unroll
    for (int m = 0; m < BM; m++) z_s[m][h] = zr[m] * td;
    __syncthreads();

    for (int m = wid; m < BM; m += 8) {
        float s = 0.0f;
#pragma unroll
        for (int j = 0; j < Hh / 32; j++) s += z_s[m][j * 32 + lane];
#pragma unroll
        for (int off = 16; off; off >>= 1)
            s += __shfl_xor_sync(0xffffffffu, s, off);
        if (lane == 0) out[b0 + m] = 1.0f / (1.0f + expf(-s));
    }
}

extern "C" void kernel_launch(void* const* d_in, const int* in_sizes, int n_in,
                              void* d_out, int out_size) {
    const float* sf        = (const float*)d_in[0];
    const float* theta     = (const float*)d_in[1];
    const float* bias      = (const float*)d_in[2];
    const float* theta_dot = (const float*)d_in[3];
    float*       out       = (float*)d_out;

    transpose_kernel<<<HV, 256>>>(theta);
    rnn_persistent<<<NBLK, 256>>>(sf, bias, theta_dot, out);
}

// round 5
// speedup vs baseline: 2.1433x; 1.1078x over previous
#include <cuda_runtime.h>
#include <math.h>

#define Bsz 2048
#define Tt  512
#define Vv  64
#define Hh  256
#define HV  320          // H + V
#define BM  16           // batch rows per block
#define BMP 20           // padded row width (floats), 16B-aligned rows
#define NBLK (Bsz / BM)  // 128 blocks
#define NTHR 512         // 16 warps; each thread: 2 cols x 4 rows

// theta packed: g_thetaT4[(k>>2)*(Hh*4) + h*4 + (k&3)]
__device__ __align__(16) float g_thetaT4[HV * Hh];

// ---------- packed f32x2 helpers ----------
__device__ __forceinline__ unsigned long long fma2(unsigned long long a,
                                                   unsigned long long b,
                                                   unsigned long long c) {
    unsigned long long d;
    asm("fma.rn.f32x2 %0, %1, %2, %3;" : "=l"(d) : "l"(a), "l"(b), "l"(c));
    return d;
}
__device__ __forceinline__ unsigned long long pack2(float x) {
    unsigned long long d;
    asm("mov.b64 %0, {%1, %1};" : "=l"(d) : "r"(__float_as_uint(x)));
    return d;
}
__device__ __forceinline__ void unpack2(unsigned long long v, float& lo, float& hi) {
    unsigned int a, b;
    asm("mov.b64 {%0, %1}, %2;" : "=r"(a), "=r"(b) : "l"(v));
    lo = __uint_as_float(a);
    hi = __uint_as_float(b);
}

// theta [H, H+V] row-major -> packed chunk layout
__global__ void transpose_kernel(const float* __restrict__ theta) {
    int idx = blockIdx.x * blockDim.x + threadIdx.x;
    if (idx >= HV * Hh) return;
    int k = idx >> 8;
    int h = idx & 255;
    g_thetaT4[(k >> 2) * (Hh * 4) + h * 4 + (k & 3)] = theta[h * HV + k];
}

// Persistent kernel: each block owns BM batch rows for ALL T steps.
// Thread layout: hb = tid & 127 -> columns (hb, hb+128); r0 = (tid>>7)*4 -> rows r0..r0+3.
__global__ void __launch_bounds__(NTHR, 1) rnn_persistent(
    const float* __restrict__ sf,        // [B, T, V]
    const float* __restrict__ bias_g,    // [1]
    const float* __restrict__ theta_dot, // [1, H]
    float* __restrict__ out)             // [B]
{
    __shared__ __align__(16) float st_p[HV][BMP];   // state+token, k-major: 25.6 KB
    __shared__ __align__(16) float z_s[BM][Hh];     // z scratch: 16 KB
    __shared__ float mean_s[BM];
    __shared__ float rstd_s[BM];

    const int tid  = threadIdx.x;
    const int hb   = tid & 127;          // column base (cols hb, hb+128)
    const int r0   = (tid >> 7) * 4;     // row group
    const int wid  = tid >> 5, lane = tid & 31;
    const int b0   = blockIdx.x * BM;

    // token-load mapping: warp wid owns row wid (16 warps, 16 rows), lane -> 2 V-values
    const int m_t = wid;
    const int v2  = lane * 2;

    const float bval = bias_g[0];
    const float td0 = theta_dot[hb];
    const float td1 = theta_dot[hb + 128];

    // ---- zero initial state ----
    for (int idx = tid; idx < HV * BMP; idx += NTHR)
        (&st_p[0][0])[idx] = 0.0f;

    // ---- stage tokens for t=0 ----
    {
        float2 tk = *reinterpret_cast<const float2*>(
            &sf[((size_t)(b0 + m_t) * Tt + 0) * Vv + v2]);
        st_p[Hh + v2 + 0][m_t] = tk.x;
        st_p[Hh + v2 + 1][m_t] = tk.y;
    }

    const float4* th0 = reinterpret_cast<const float4*>(g_thetaT4) + hb;
    const float4* th1 = th0 + 128;

    float zr[8];   // [col][row]: zr[c*4 + rr], rows r0..r0+3

    for (int t = 0; t < Tt; t++) {
        __syncthreads();   // (d) state + token writes visible

        // prefetch next token (overlaps GEMM)
        float2 tok;
        const bool havet = (t + 1 < Tt);
        if (havet) {
            tok = *reinterpret_cast<const float2*>(
                &sf[((size_t)(b0 + m_t) * Tt + (t + 1)) * Vv + v2]);
        }

        // ---------- GEMM: 2 cols x 4 rows per thread ----------
        unsigned long long acc[4];   // [col][rowpair]
        acc[0] = acc[1] = acc[2] = acc[3] = pack2(bval);

        float4 a0 = th0[0];
        float4 a1 = th1[0];
#pragma unroll 4
        for (int c = 0; c < HV / 4; c++) {
            int cn = (c + 1 < HV / 4) ? c + 1 : c;
            float4 n0 = th0[cn * Hh];        // prefetch next chunk
            float4 n1 = th1[cn * Hh];
            float t0a[4], t1a[4];
            *reinterpret_cast<float4*>(t0a) = a0;
            *reinterpret_cast<float4*>(t1a) = a1;
#pragma unroll
            for (int kk = 0; kk < 4; kk++) {
                unsigned long long p0 = pack2(t0a[kk]);
                unsigned long long p1 = pack2(t1a[kk]);
                ulonglong2 s = *reinterpret_cast<const ulonglong2*>(
                    &st_p[c * 4 + kk][r0]);        // broadcast LDS.128 (4 rows)
                acc[0] = fma2(s.x, p0, acc[0]);
                acc[1] = fma2(s.y, p0, acc[1]);
                acc[2] = fma2(s.x, p1, acc[2]);
                acc[3] = fma2(s.y, p1, acc[3]);
            }
            a0 = n0;
            a1 = n1;
        }

        // unpack z, stage into z_s
        unpack2(acc[0], zr[0], zr[1]);
        unpack2(acc[1], zr[2], zr[3]);
        unpack2(acc[2], zr[4], zr[5]);
        unpack2(acc[3], zr[6], zr[7]);
#pragma unroll
        for (int rr = 0; rr < 4; rr++) {
            z_s[r0 + rr][hb]       = zr[rr];
            z_s[r0 + rr][hb + 128] = zr[4 + rr];
        }

        __syncthreads();   // (b) z_s ready; st_p GEMM reads done

        // ---------- per-row mean / Bessel std: warp wid -> row wid ----------
        {
            const int m = wid;
            float s = 0.0f, ss = 0.0f;
#pragma unroll
            for (int j = 0; j < Hh / 32; j++) {
                float v = z_s[m][j * 32 + lane];
                s += v;
                ss = fmaf(v, v, ss);
            }
#pragma unroll
            for (int off = 16; off; off >>= 1) {
                s  += __shfl_xor_sync(0xffffffffu, s, off);
                ss += __shfl_xor_sync(0xffffffffu, ss, off);
            }
            if (lane == 0) {
                float mean = s * (1.0f / Hh);
                float var  = (ss - (float)Hh * mean * mean) * (1.0f / (Hh - 1));
                var = fmaxf(var, 1e-30f);
                float r = rsqrtf(var);
                r = r * (1.5f - 0.5f * var * r * r);   // Newton refine
                mean_s[m] = mean;
                rstd_s[m] = r;
            }
        }

        // stage next tokens (st_p token rows free after bar (b))
        if (havet) {
            st_p[Hh + v2 + 0][m_t] = tok.x;
            st_p[Hh + v2 + 1][m_t] = tok.y;
        }

        __syncthreads();   // (c) mean/rstd ready

        // ---------- layernorm apply + relu, write state ----------
        float4 o0, o1;
        {
            float mn[4], rs[4];
#pragma unroll
            for (int rr = 0; rr < 4; rr++) { mn[rr] = mean_s[r0 + rr]; rs[rr] = rstd_s[r0 + rr]; }
            o0.x = fmaxf((zr[0] - mn[0]) * rs[0], 0.0f);
            o0.y = fmaxf((zr[1] - mn[1]) * rs[1], 0.0f);
            o0.z = fmaxf((zr[2] - mn[2]) * rs[2], 0.0f);
            o0.w = fmaxf((zr[3] - mn[3]) * rs[3], 0.0f);
            o1.x = fmaxf((zr[4] - mn[0]) * rs[0], 0.0f);
            o1.y = fmaxf((zr[5] - mn[1]) * rs[1], 0.0f);
            o1.z = fmaxf((zr[6] - mn[2]) * rs[2], 0.0f);
            o1.w = fmaxf((zr[7] - mn[3]) * rs[3], 0.0f);
        }
        *reinterpret_cast<float4*>(&st_p[hb][r0])       = o0;
        *reinterpret_cast<float4*>(&st_p[hb + 128][r0]) = o1;
        zr[0] = o0.x; zr[1] = o0.y; zr[2] = o0.z; zr[3] = o0.w;
        zr[4] = o1.x; zr[5] = o1.y; zr[6] = o1.z; zr[7] = o1.w;
    }

    // ---------- logits: out[b] = sigmoid(sum_h state[b,h] * theta_dot[h]) ----------
#pragma unroll
    for (int rr = 0; rr < 4; rr++) {
        z_s[r0 + rr][hb]       = zr[rr]     * td0;
        z_s[r0 + rr][hb + 128] = zr[4 + rr] * td1;
    }
    __syncthreads();

    {
        const int m = wid;
        float s = 0.0f;
#pragma unroll
        for (int j = 0; j < Hh / 32; j++) s += z_s[m][j * 32 + lane];
#pragma unroll
        for (int off = 16; off; off >>= 1)
            s += __shfl_xor_sync(0xffffffffu, s, off);
        if (lane == 0) out[b0 + m] = 1.0f / (1.0f + expf(-s));
    }
}

extern "C" void kernel_launch(void* const* d_in, const int* in_sizes, int n_in,
                              void* d_out, int out_size) {
    const float* sf        = (const float*)d_in[0];
    const float* theta     = (const float*)d_in[1];
    const float* bias      = (const float*)d_in[2];
    const float* theta_dot = (const float*)d_in[3];
    float*       out       = (float*)d_out;

    transpose_kernel<<<HV, 256>>>(theta);
    rnn_persistent<<<NBLK, NTHR>>>(sf, bias, theta_dot, out);
}

// round 6
// speedup vs baseline: 2.1466x; 1.0016x over previous
#include <cuda_runtime.h>
#include <math.h>

#define Bsz 2048
#define Tt  512
#define Vv  64
#define Hh  256
#define HV  320          // H + V
#define BM  16           // batch rows per block
#define BMP 20           // padded row width (floats), 16B-aligned rows
#define NBLK (Bsz / BM)  // 128 blocks
#define NTHR 512         // 16 warps; each thread: 2 cols x 4 rows

// theta packed: g_thetaT4[(k>>2)*(Hh*4) + h*4 + (k&3)]
__device__ __align__(16) float g_thetaT4[HV * Hh];

// ---------- packed f32x2 helpers ----------
__device__ __forceinline__ unsigned long long fma2(unsigned long long a,
                                                   unsigned long long b,
                                                   unsigned long long c) {
    unsigned long long d;
    asm("fma.rn.f32x2 %0, %1, %2, %3;" : "=l"(d) : "l"(a), "l"(b), "l"(c));
    return d;
}
__device__ __forceinline__ unsigned long long pack2(float x) {
    unsigned long long d;
    asm("mov.b64 %0, {%1, %1};" : "=l"(d) : "r"(__float_as_uint(x)));
    return d;
}
__device__ __forceinline__ void unpack2(unsigned long long v, float& lo, float& hi) {
    unsigned int a, b;
    asm("mov.b64 {%0, %1}, %2;" : "=r"(a), "=r"(b) : "l"(v));
    lo = __uint_as_float(a);
    hi = __uint_as_float(b);
}

// theta [H, H+V] row-major -> packed chunk layout
__global__ void transpose_kernel(const float* __restrict__ theta) {
    int idx = blockIdx.x * blockDim.x + threadIdx.x;
    if (idx >= HV * Hh) return;
    int k = idx >> 8;
    int h = idx & 255;
    g_thetaT4[(k >> 2) * (Hh * 4) + h * 4 + (k & 3)] = theta[h * HV + k];
}

// Persistent kernel: each block owns BM batch rows for ALL T steps.
// Thread layout: hb = tid & 127 -> columns (hb, hb+128); r0 = (tid>>7)*4 -> rows r0..r0+3.
__global__ void __launch_bounds__(NTHR, 1) rnn_persistent(
    const float* __restrict__ sf,        // [B, T, V]
    const float* __restrict__ bias_g,    // [1]
    const float* __restrict__ theta_dot, // [1, H]
    float* __restrict__ out)             // [B]
{
    __shared__ __align__(16) float st_p[HV][BMP];   // state+token, k-major: 25.6 KB
    __shared__ __align__(16) float z_s[BM][Hh];     // z scratch: 16 KB
    __shared__ float mean_s[BM];
    __shared__ float rstd_s[BM];

    const int tid  = threadIdx.x;
    const int hb   = tid & 127;          // column base (cols hb, hb+128)
    const int r0   = (tid >> 7) * 4;     // row group
    const int wid  = tid >> 5, lane = tid & 31;
    const int b0   = blockIdx.x * BM;

    // token-load mapping: warp wid owns row wid (16 warps, 16 rows), lane -> 2 V-values
    const int m_t = wid;
    const int v2  = lane * 2;

    const float bval = bias_g[0];
    const float td0 = theta_dot[hb];
    const float td1 = theta_dot[hb + 128];

    // ---- zero initial state ----
    for (int idx = tid; idx < HV * BMP; idx += NTHR)
        (&st_p[0][0])[idx] = 0.0f;

    // ---- stage tokens for t=0 ----
    {
        float2 tk = *reinterpret_cast<const float2*>(
            &sf[((size_t)(b0 + m_t) * Tt + 0) * Vv + v2]);
        st_p[Hh + v2 + 0][m_t] = tk.x;
        st_p[Hh + v2 + 1][m_t] = tk.y;
    }

    const float4* th0 = reinterpret_cast<const float4*>(g_thetaT4) + hb;
    const float4* th1 = th0 + 128;

    float zr[8];   // [col][row]: zr[c*4 + rr], rows r0..r0+3

    for (int t = 0; t < Tt; t++) {
        __syncthreads();   // (d) state + token writes visible

        // prefetch next token (overlaps GEMM)
        float2 tok;
        const bool havet = (t + 1 < Tt);
        if (havet) {
            tok = *reinterpret_cast<const float2*>(
                &sf[((size_t)(b0 + m_t) * Tt + (t + 1)) * Vv + v2]);
        }

        // ---------- GEMM: 2 cols x 4 rows per thread ----------
        unsigned long long acc[4];   // [col][rowpair]
        acc[0] = acc[1] = acc[2] = acc[3] = pack2(bval);

        float4 a0 = th0[0];
        float4 a1 = th1[0];
#pragma unroll 4
        for (int c = 0; c < HV / 4; c++) {
            int cn = (c + 1 < HV / 4) ? c + 1 : c;
            float4 n0 = th0[cn * Hh];        // prefetch next chunk
            float4 n1 = th1[cn * Hh];
            float t0a[4], t1a[4];
            *reinterpret_cast<float4*>(t0a) = a0;
            *reinterpret_cast<float4*>(t1a) = a1;
#pragma unroll
            for (int kk = 0; kk < 4; kk++) {
                unsigned long long p0 = pack2(t0a[kk]);
                unsigned long long p1 = pack2(t1a[kk]);
                ulonglong2 s = *reinterpret_cast<const ulonglong2*>(
                    &st_p[c * 4 + kk][r0]);        // broadcast LDS.128 (4 rows)
                acc[0] = fma2(s.x, p0, acc[0]);
                acc[1] = fma2(s.y, p0, acc[1]);
                acc[2] = fma2(s.x, p1, acc[2]);
                acc[3] = fma2(s.y, p1, acc[3]);
            }
            a0 = n0;
            a1 = n1;
        }

        // unpack z, stage into z_s
        unpack2(acc[0], zr[0], zr[1]);
        unpack2(acc[1], zr[2], zr[3]);
        unpack2(acc[2], zr[4], zr[5]);
        unpack2(acc[3], zr[6], zr[7]);
#pragma unroll
        for (int rr = 0; rr < 4; rr++) {
            z_s[r0 + rr][hb]       = zr[rr];
            z_s[r0 + rr][hb + 128] = zr[4 + rr];
        }

        __syncthreads();   // (b) z_s ready; st_p GEMM reads done

        // ---------- per-row mean / Bessel std: warp wid -> row wid ----------
        {
            const int m = wid;
            float s = 0.0f, ss = 0.0f;
#pragma unroll
            for (int j = 0; j < Hh / 32; j++) {
                float v = z_s[m][j * 32 + lane];
                s += v;
                ss = fmaf(v, v, ss);
            }
#pragma unroll
            for (int off = 16; off; off >>= 1) {
                s  += __shfl_xor_sync(0xffffffffu, s, off);
                ss += __shfl_xor_sync(0xffffffffu, ss, off);
            }
            if (lane == 0) {
                float mean = s * (1.0f / Hh);
                float var  = (ss - (float)Hh * mean * mean) * (1.0f / (Hh - 1));
                var = fmaxf(var, 1e-30f);
                float r = rsqrtf(var);
                r = r * (1.5f - 0.5f * var * r * r);   // Newton refine
                mean_s[m] = mean;
                rstd_s[m] = r;
            }
        }

        // stage next tokens (st_p token rows free after bar (b))
        if (havet) {
            st_p[Hh + v2 + 0][m_t] = tok.x;
            st_p[Hh + v2 + 1][m_t] = tok.y;
        }

        __syncthreads();   // (c) mean/rstd ready

        // ---------- layernorm apply + relu, write state ----------
        float4 o0, o1;
        {
            float mn[4], rs[4];
#pragma unroll
            for (int rr = 0; rr < 4; rr++) { mn[rr] = mean_s[r0 + rr]; rs[rr] = rstd_s[r0 + rr]; }
            o0.x = fmaxf((zr[0] - mn[0]) * rs[0], 0.0f);
            o0.y = fmaxf((zr[1] - mn[1]) * rs[1], 0.0f);
            o0.z = fmaxf((zr[2] - mn[2]) * rs[2], 0.0f);
            o0.w = fmaxf((zr[3] - mn[3]) * rs[3], 0.0f);
            o1.x = fmaxf((zr[4] - mn[0]) * rs[0], 0.0f);
            o1.y = fmaxf((zr[5] - mn[1]) * rs[1], 0.0f);
            o1.z = fmaxf((zr[6] - mn[2]) * rs[2], 0.0f);
            o1.w = fmaxf((zr[7] - mn[3]) * rs[3], 0.0f);
        }
        *reinterpret_cast<float4*>(&st_p[hb][r0])       = o0;
        *reinterpret_cast<float4*>(&st_p[hb + 128][r0]) = o1;
        zr[0] = o0.x; zr[1] = o0.y; zr[2] = o0.z; zr[3] = o0.w;
        zr[4] = o1.x; zr[5] = o1.y; zr[6] = o1.z; zr[7] = o1.w;
    }

    // ---------- logits: out[b] = sigmoid(sum_h state[b,h] * theta_dot[h]) ----------
#pragma unroll
    for (int rr = 0; rr < 4; rr++) {
        z_s[r0 + rr][hb]       = zr[rr]     * td0;
        z_s[r0 + rr][hb + 128] = zr[4 + rr] * td1;
    }
    __syncthreads();

    {
        const int m = wid;
        float s = 0.0f;
#pragma unroll
        for (int j = 0; j < Hh / 32; j++) s += z_s[m][j * 32 + lane];
#pragma unroll
        for (int off = 16; off; off >>= 1)
            s += __shfl_xor_sync(0xffffffffu, s, off);
        if (lane == 0) out[b0 + m] = 1.0f / (1.0f + expf(-s));
    }
}

extern "C" void kernel_launch(void* const* d_in, const int* in_sizes, int n_in,
                              void* d_out, int out_size) {
    const float* sf        = (const float*)d_in[0];
    const float* theta     = (const float*)d_in[1];
    const float* bias      = (const float*)d_in[2];
    const float* theta_dot = (const float*)d_in[3];
    float*       out       = (float*)d_out;

    transpose_kernel<<<HV, 256>>>(theta);
    rnn_persistent<<<NBLK, NTHR>>>(sf, bias, theta_dot, out);
}

// round 7
// speedup vs baseline: 2.1487x; 1.0010x over previous
#include <cuda_runtime.h>
#include <math.h>

#define Bsz 2048
#define Tt  512
#define Vv  64
#define Hh  256
#define HV  320          // H + V
#define BM  16           // batch rows per block
#define BMP 20           // padded row width (floats), 16B-aligned rows
#define NBLK (Bsz / BM)  // 128 blocks
#define NTHR 512         // 16 warps; each thread: 2 cols x 4 rows

// theta packed: g_thetaT4[(k>>2)*(Hh*4) + h*4 + (k&3)]
__device__ __align__(16) float g_thetaT4[HV * Hh];

// ---------- packed f32x2 helpers ----------
__device__ __forceinline__ unsigned long long fma2(unsigned long long a,
                                                   unsigned long long b,
                                                   unsigned long long c) {
    unsigned long long d;
    asm("fma.rn.f32x2 %0, %1, %2, %3;" : "=l"(d) : "l"(a), "l"(b), "l"(c));
    return d;
}
__device__ __forceinline__ unsigned long long pack2(float x) {
    unsigned long long d;
    asm("mov.b64 %0, {%1, %1};" : "=l"(d) : "r"(__float_as_uint(x)));
    return d;
}
__device__ __forceinline__ void unpack2(unsigned long long v, float& lo, float& hi) {
    unsigned int a, b;
    asm("mov.b64 {%0, %1}, %2;" : "=r"(a), "=r"(b) : "l"(v));
    lo = __uint_as_float(a);
    hi = __uint_as_float(b);
}

// theta [H, H+V] row-major -> packed chunk layout
__global__ void transpose_kernel(const float* __restrict__ theta) {
    int idx = blockIdx.x * blockDim.x + threadIdx.x;
    if (idx >= HV * Hh) return;
    int k = idx >> 8;
    int h = idx & 255;
    g_thetaT4[(k >> 2) * (Hh * 4) + h * 4 + (k & 3)] = theta[h * HV + k];
}

// Persistent kernel: each block owns BM batch rows for ALL T steps.
// Thread layout: hb = tid & 127 -> columns (hb, hb+128); r0 = (tid>>7)*4 -> rows r0..r0+3.
__global__ void __launch_bounds__(NTHR, 1) rnn_persistent(
    const float* __restrict__ sf,        // [B, T, V]
    const float* __restrict__ bias_g,    // [1]
    const float* __restrict__ theta_dot, // [1, H]
    float* __restrict__ out)             // [B]
{
    __shared__ __align__(16) float st_p[HV][BMP];   // state+token, k-major: 25.6 KB
    __shared__ __align__(16) float z_s[BM][Hh];     // z scratch: 16 KB
    __shared__ float mean_s[BM];
    __shared__ float rstd_s[BM];

    const int tid  = threadIdx.x;
    const int hb   = tid & 127;          // column base (cols hb, hb+128)
    const int r0   = (tid >> 7) * 4;     // row group
    const int wid  = tid >> 5, lane = tid & 31;
    const int b0   = blockIdx.x * BM;

    // token-load mapping: warp wid owns row wid (16 warps, 16 rows), lane -> 2 V-values
    const int m_t = wid;
    const int v2  = lane * 2;

    const float bval = bias_g[0];
    const float td0 = theta_dot[hb];
    const float td1 = theta_dot[hb + 128];

    // ---- zero initial state ----
    for (int idx = tid; idx < HV * BMP; idx += NTHR)
        (&st_p[0][0])[idx] = 0.0f;

    // ---- stage tokens for t=0 ----
    {
        float2 tk = *reinterpret_cast<const float2*>(
            &sf[((size_t)(b0 + m_t) * Tt + 0) * Vv + v2]);
        st_p[Hh + v2 + 0][m_t] = tk.x;
        st_p[Hh + v2 + 1][m_t] = tk.y;
    }

    const float4* th0 = reinterpret_cast<const float4*>(g_thetaT4) + hb;
    const float4* th1 = th0 + 128;

    float zr[8];   // [col][row]: zr[c*4 + rr], rows r0..r0+3

    for (int t = 0; t < Tt; t++) {
        __syncthreads();   // (d) state + token writes visible

        // prefetch next token (overlaps GEMM)
        float2 tok;
        const bool havet = (t + 1 < Tt);
        if (havet) {
            tok = *reinterpret_cast<const float2*>(
                &sf[((size_t)(b0 + m_t) * Tt + (t + 1)) * Vv + v2]);
        }

        // ---------- GEMM: 2 cols x 4 rows per thread ----------
        unsigned long long acc[4];   // [col][rowpair]
        acc[0] = acc[1] = acc[2] = acc[3] = pack2(bval);

        float4 a0 = th0[0];
        float4 a1 = th1[0];
#pragma unroll 4
        for (int c = 0; c < HV / 4; c++) {
            int cn = (c + 1 < HV / 4) ? c + 1 : c;
            float4 n0 = th0[cn * Hh];        // prefetch next chunk
            float4 n1 = th1[cn * Hh];
            float t0a[4], t1a[4];
            *reinterpret_cast<float4*>(t0a) = a0;
            *reinterpret_cast<float4*>(t1a) = a1;
#pragma unroll
            for (int kk = 0; kk < 4; kk++) {
                unsigned long long p0 = pack2(t0a[kk]);
                unsigned long long p1 = pack2(t1a[kk]);
                ulonglong2 s = *reinterpret_cast<const ulonglong2*>(
                    &st_p[c * 4 + kk][r0]);        // broadcast LDS.128 (4 rows)
                acc[0] = fma2(s.x, p0, acc[0]);
                acc[1] = fma2(s.y, p0, acc[1]);
                acc[2] = fma2(s.x, p1, acc[2]);
                acc[3] = fma2(s.y, p1, acc[3]);
            }
            a0 = n0;
            a1 = n1;
        }

        // unpack z, stage into z_s
        unpack2(acc[0], zr[0], zr[1]);
        unpack2(acc[1], zr[2], zr[3]);
        unpack2(acc[2], zr[4], zr[5]);
        unpack2(acc[3], zr[6], zr[7]);
#pragma unroll
        for (int rr = 0; rr < 4; rr++) {
            z_s[r0 + rr][hb]       = zr[rr];
            z_s[r0 + rr][hb + 128] = zr[4 + rr];
        }

        __syncthreads();   // (b) z_s ready; st_p GEMM reads done

        // ---------- per-row mean / Bessel std: warp wid -> row wid ----------
        {
            const int m = wid;
            float s = 0.0f, ss = 0.0f;
#pragma unroll
            for (int j = 0; j < Hh / 32; j++) {
                float v = z_s[m][j * 32 + lane];
                s += v;
                ss = fmaf(v, v, ss);
            }
#pragma unroll
            for (int off = 16; off; off >>= 1) {
                s  += __shfl_xor_sync(0xffffffffu, s, off);
                ss += __shfl_xor_sync(0xffffffffu, ss, off);
            }
            if (lane == 0) {
                float mean = s * (1.0f / Hh);
                float var  = (ss - (float)Hh * mean * mean) * (1.0f / (Hh - 1));
                var = fmaxf(var, 1e-30f);
                float r = rsqrtf(var);
                r = r * (1.5f - 0.5f * var * r * r);   // Newton refine
                mean_s[m] = mean;
                rstd_s[m] = r;
            }
        }

        // stage next tokens (st_p token rows free after bar (b))
        if (havet) {
            st_p[Hh + v2 + 0][m_t] = tok.x;
            st_p[Hh + v2 + 1][m_t] = tok.y;
        }

        __syncthreads();   // (c) mean/rstd ready

        // ---------- layernorm apply + relu, write state ----------
        float4 o0, o1;
        {
            float mn[4], rs[4];
#pragma unroll
            for (int rr = 0; rr < 4; rr++) { mn[rr] = mean_s[r0 + rr]; rs[rr] = rstd_s[r0 + rr]; }
            o0.x = fmaxf((zr[0] - mn[0]) * rs[0], 0.0f);
            o0.y = fmaxf((zr[1] - mn[1]) * rs[1], 0.0f);
            o0.z = fmaxf((zr[2] - mn[2]) * rs[2], 0.0f);
            o0.w = fmaxf((zr[3] - mn[3]) * rs[3], 0.0f);
            o1.x = fmaxf((zr[4] - mn[0]) * rs[0], 0.0f);
            o1.y = fmaxf((zr[5] - mn[1]) * rs[1], 0.0f);
            o1.z = fmaxf((zr[6] - mn[2]) * rs[2], 0.0f);
            o1.w = fmaxf((zr[7] - mn[3]) * rs[3], 0.0f);
        }
        *reinterpret_cast<float4*>(&st_p[hb][r0])       = o0;
        *reinterpret_cast<float4*>(&st_p[hb + 128][r0]) = o1;
        zr[0] = o0.x; zr[1] = o0.y; zr[2] = o0.z; zr[3] = o0.w;
        zr[4] = o1.x; zr[5] = o1.y; zr[6] = o1.z; zr[7] = o1.w;
    }

    // ---------- logits: out[b] = sigmoid(sum_h state[b,h] * theta_dot[h]) ----------
#pragma unroll
    for (int rr = 0; rr < 4; rr++) {
        z_s[r0 + rr][hb]       = zr[rr]     * td0;
        z_s[r0 + rr][hb + 128] = zr[4 + rr] * td1;
    }
    __syncthreads();

    {
        const int m = wid;
        float s = 0.0f;
#pragma unroll
        for (int j = 0; j < Hh / 32; j++) s += z_s[m][j * 32 + lane];
#pragma unroll
        for (int off = 16; off; off >>= 1)
            s += __shfl_xor_sync(0xffffffffu, s, off);
        if (lane == 0) out[b0 + m] = 1.0f / (1.0f + expf(-s));
    }
}

extern "C" void kernel_launch(void* const* d_in, const int* in_sizes, int n_in,
                              void* d_out, int out_size) {
    const float* sf        = (const float*)d_in[0];
    const float* theta     = (const float*)d_in[1];
    const float* bias      = (const float*)d_in[2];
    const float* theta_dot = (const float*)d_in[3];
    float*       out       = (float*)d_out;

    transpose_kernel<<<HV, 256>>>(theta);
    rnn_persistent<<<NBLK, NTHR>>>(sf, bias, theta_dot, out);
}

// round 8
// speedup vs baseline: 2.3485x; 1.0930x over previous
#include <cuda_runtime.h>
#include <math.h>

#define Bsz 2048
#define Tt  512
#define Vv  64
#define Hh  256
#define HV  320          // H + V
#define BM  16           // batch rows per block
#define BMP 20           // padded row width (floats), 16B-aligned rows
#define NBLK (Bsz / BM)  // 128 blocks
#define NTHR 256         // 8 warps; each thread: 2 cols x 8 rows

// theta packed: g_thetaT4[(k>>2)*(Hh*4) + h*4 + (k&3)]
__device__ __align__(16) float g_thetaT4[HV * Hh];

// ---------- packed f32x2 helpers ----------
__device__ __forceinline__ unsigned long long fma2(unsigned long long a,
                                                   unsigned long long b,
                                                   unsigned long long c) {
    unsigned long long d;
    asm("fma.rn.f32x2 %0, %1, %2, %3;" : "=l"(d) : "l"(a), "l"(b), "l"(c));
    return d;
}
__device__ __forceinline__ unsigned long long pack2(float x) {
    unsigned long long d;
    asm("mov.b64 %0, {%1, %1};" : "=l"(d) : "r"(__float_as_uint(x)));
    return d;
}
__device__ __forceinline__ void unpack2(unsigned long long v, float& lo, float& hi) {
    unsigned int a, b;
    asm("mov.b64 {%0, %1}, %2;" : "=r"(a), "=r"(b) : "l"(v));
    lo = __uint_as_float(a);
    hi = __uint_as_float(b);
}

// theta [H, H+V] row-major -> packed chunk layout
__global__ void transpose_kernel(const float* __restrict__ theta) {
    int idx = blockIdx.x * blockDim.x + threadIdx.x;
    if (idx >= HV * Hh) return;
    int k = idx >> 8;
    int h = idx & 255;
    g_thetaT4[(k >> 2) * (Hh * 4) + h * 4 + (k & 3)] = theta[h * HV + k];
}

// Persistent kernel: each block owns BM batch rows for ALL T steps.
// Thread layout: hb = tid & 127 -> cols (hb, hb+128); r0 = (tid>>7)*8 -> rows r0..r0+7.
__global__ void __launch_bounds__(NTHR, 1) rnn_persistent(
    const float* __restrict__ sf,        // [B, T, V]
    const float* __restrict__ bias_g,    // [1]
    const float* __restrict__ theta_dot, // [1, H]
    float* __restrict__ out)             // [B]
{
    __shared__ __align__(16) float st_p[HV][BMP];   // state+token, k-major: 25.6 KB
    __shared__ __align__(16) float z_s[BM][Hh];     // z scratch: 16 KB
    __shared__ float mean_s[BM];
    __shared__ float rstd_s[BM];

    const int tid  = threadIdx.x;
    const int hb   = tid & 127;          // column base (cols hb, hb+128)
    const int r0   = (tid >> 7) * 8;     // row group: rows r0..r0+7
    const int wid  = tid >> 5, lane = tid & 31;
    const int b0   = blockIdx.x * BM;

    // token-load mapping: thread -> (row m_t, float4 group v4)
    const int m_t = tid >> 4;            // 0..15
    const int v4  = (tid & 15) * 4;      // 0,4,..,60

    const float bval = bias_g[0];
    const float td0 = theta_dot[hb];
    const float td1 = theta_dot[hb + 128];

    // ---- zero initial state ----
    for (int idx = tid; idx < HV * BMP; idx += NTHR)
        (&st_p[0][0])[idx] = 0.0f;

    // ---- stage tokens for t=0 ----
    {
        float4 tk = *reinterpret_cast<const float4*>(
            &sf[((size_t)(b0 + m_t) * Tt + 0) * Vv + v4]);
        st_p[Hh + v4 + 0][m_t] = tk.x;
        st_p[Hh + v4 + 1][m_t] = tk.y;
        st_p[Hh + v4 + 2][m_t] = tk.z;
        st_p[Hh + v4 + 3][m_t] = tk.w;
    }

    const float4* th0 = reinterpret_cast<const float4*>(g_thetaT4) + hb;
    const float4* th1 = th0 + 128;

    float zr[16];   // [col(2)][row(8)]

    for (int t = 0; t < Tt; t++) {
        __syncthreads();   // (d) state + token writes visible

        // prefetch next token (overlaps GEMM)
        float4 tok;
        const bool havet = (t + 1 < Tt);
        if (havet) {
            tok = *reinterpret_cast<const float4*>(
                &sf[((size_t)(b0 + m_t) * Tt + (t + 1)) * Vv + v4]);
        }

        // ---------- GEMM: 2 cols x 8 rows per thread ----------
        unsigned long long acc[8];   // [col(2)][rowpair(4)]
#pragma unroll
        for (int j = 0; j < 8; j++) acc[j] = pack2(bval);

        float4 a0 = th0[0];
        float4 a1 = th1[0];
#pragma unroll 4
        for (int c = 0; c < HV / 4; c++) {
            int cn = (c + 1 < HV / 4) ? c + 1 : c;
            float4 n0 = th0[cn * Hh];        // prefetch next chunk
            float4 n1 = th1[cn * Hh];
            float t0a[4], t1a[4];
            *reinterpret_cast<float4*>(t0a) = a0;
            *reinterpret_cast<float4*>(t1a) = a1;
#pragma unroll
            for (int kk = 0; kk < 4; kk++) {
                unsigned long long p0 = pack2(t0a[kk]);
                unsigned long long p1 = pack2(t1a[kk]);
                // broadcast LDS.128 x2: 8 row-values for this k
                ulonglong2 sA = *reinterpret_cast<const ulonglong2*>(
                    &st_p[c * 4 + kk][r0]);          // rows r0..r0+3
                ulonglong2 sB = *reinterpret_cast<const ulonglong2*>(
                    &st_p[c * 4 + kk][r0 + 4]);      // rows r0+4..r0+7
                acc[0] = fma2(sA.x, p0, acc[0]);
                acc[1] = fma2(sA.y, p0, acc[1]);
                acc[2] = fma2(sB.x, p0, acc[2]);
                acc[3] = fma2(sB.y, p0, acc[3]);
                acc[4] = fma2(sA.x, p1, acc[4]);
                acc[5] = fma2(sA.y, p1, acc[5]);
                acc[6] = fma2(sB.x, p1, acc[6]);
                acc[7] = fma2(sB.y, p1, acc[7]);
            }
            a0 = n0;
            a1 = n1;
        }

        // unpack z, stage into z_s
#pragma unroll
        for (int j = 0; j < 8; j++) unpack2(acc[j], zr[2 * j], zr[2 * j + 1]);
#pragma unroll
        for (int rr = 0; rr < 8; rr++) {
            z_s[r0 + rr][hb]       = zr[rr];        // col hb
            z_s[r0 + rr][hb + 128] = zr[8 + rr];    // col hb+128
        }

        __syncthreads();   // (b) z_s ready; st_p GEMM reads done

        // ---------- per-row mean / Bessel std: 8 warps x 2 rows ----------
        for (int m = wid; m < BM; m += 8) {
            float s = 0.0f, ss = 0.0f;
#pragma unroll
            for (int j = 0; j < Hh / 32; j++) {
                float v = z_s[m][j * 32 + lane];
                s += v;
                ss = fmaf(v, v, ss);
            }
#pragma unroll
            for (int off = 16; off; off >>= 1) {
                s  += __shfl_xor_sync(0xffffffffu, s, off);
                ss += __shfl_xor_sync(0xffffffffu, ss, off);
            }
            if (lane == 0) {
                float mean = s * (1.0f / Hh);
                float var  = (ss - (float)Hh * mean * mean) * (1.0f / (Hh - 1));
                var = fmaxf(var, 1e-30f);
                float r = rsqrtf(var);
                r = r * (1.5f - 0.5f * var * r * r);   // Newton refine
                mean_s[m] = mean;
                rstd_s[m] = r;
            }
        }

        // stage next tokens (st_p token rows free after bar (b))
        if (havet) {
            st_p[Hh + v4 + 0][m_t] = tok.x;
            st_p[Hh + v4 + 1][m_t] = tok.y;
            st_p[Hh + v4 + 2][m_t] = tok.z;
            st_p[Hh + v4 + 3][m_t] = tok.w;
        }

        __syncthreads();   // (c) mean/rstd ready

        // ---------- layernorm apply + relu, write state (vectorized STS.128) ----------
        {
            float4 o[4];   // [col0 rows r0..r0+7] as 2x float4, then col1
            float mn[8], rs[8];
#pragma unroll
            for (int rr = 0; rr < 8; rr++) { mn[rr] = mean_s[r0 + rr]; rs[rr] = rstd_s[r0 + rr]; }
#pragma unroll
            for (int rr = 0; rr < 8; rr++) {
                zr[rr]     = fmaxf((zr[rr]     - mn[rr]) * rs[rr], 0.0f);
                zr[8 + rr] = fmaxf((zr[8 + rr] - mn[rr]) * rs[rr], 0.0f);
            }
            o[0] = make_float4(zr[0], zr[1], zr[2], zr[3]);
            o[1] = make_float4(zr[4], zr[5], zr[6], zr[7]);
            o[2] = make_float4(zr[8], zr[9], zr[10], zr[11]);
            o[3] = make_float4(zr[12], zr[13], zr[14], zr[15]);
            *reinterpret_cast<float4*>(&st_p[hb][r0])           = o[0];
            *reinterpret_cast<float4*>(&st_p[hb][r0 + 4])       = o[1];
            *reinterpret_cast<float4*>(&st_p[hb + 128][r0])     = o[2];
            *reinterpret_cast<float4*>(&st_p[hb + 128][r0 + 4]) = o[3];
        }
    }

    // ---------- logits: out[b] = sigmoid(sum_h state[b,h] * theta_dot[h]) ----------
#pragma unroll
    for (int rr = 0; rr < 8; rr++) {
        z_s[r0 + rr][hb]       = zr[rr]     * td0;
        z_s[r0 + rr][hb + 128] = zr[8 + rr] * td1;
    }
    __syncthreads();

    for (int m = wid; m < BM; m += 8) {
        float s = 0.0f;
#pragma unroll
        for (int j = 0; j < Hh / 32; j++) s += z_s[m][j * 32 + lane];
#pragma unroll
        for (int off = 16; off; off >>= 1)
            s += __shfl_xor_sync(0xffffffffu, s, off);
        if (lane == 0) out[b0 + m] = 1.0f / (1.0f + expf(-s));
    }
}

extern "C" void kernel_launch(void* const* d_in, const int* in_sizes, int n_in,
                              void* d_out, int out_size) {
    const float* sf        = (const float*)d_in[0];
    const float* theta     = (const float*)d_in[1];
    const float* bias      = (const float*)d_in[2];
    const float* theta_dot = (const float*)d_in[3];
    float*       out       = (float*)d_out;

    transpose_kernel<<<HV, 256>>>(theta);
    rnn_persistent<<<NBLK, NTHR>>>(sf, bias, theta_dot, out);
}

// round 9
// speedup vs baseline: 2.3820x; 1.0143x over previous
#include <cuda_runtime.h>
#include <math.h>

#define Bsz 2048
#define Tt  512
#define Vv  64
#define Hh  256
#define HV  320          // H + V
#define BM  16           // batch rows per block
#define BMP 20           // padded row width (floats), 16B-aligned rows
#define NBLK (Bsz / BM)  // 128 blocks
#define NTHR 256         // 8 warps; each thread: 2 cols x 8 rows
#define NC   (HV / 4)    // 80 k-chunks

// theta packed: g_thetaT4[(k>>2)*(Hh*4) + h*4 + (k&3)]
__device__ __align__(16) float g_thetaT4[HV * Hh];

// ---------- packed f32x2 helpers ----------
__device__ __forceinline__ unsigned long long fma2(unsigned long long a,
                                                   unsigned long long b,
                                                   unsigned long long c) {
    unsigned long long d;
    asm("fma.rn.f32x2 %0, %1, %2, %3;" : "=l"(d) : "l"(a), "l"(b), "l"(c));
    return d;
}
__device__ __forceinline__ unsigned long long pack2(float x) {
    unsigned long long d;
    asm("mov.b64 %0, {%1, %1};" : "=l"(d) : "r"(__float_as_uint(x)));
    return d;
}
__device__ __forceinline__ void unpack2(unsigned long long v, float& lo, float& hi) {
    unsigned int a, b;
    asm("mov.b64 {%0, %1}, %2;" : "=r"(a), "=r"(b) : "l"(v));
    lo = __uint_as_float(a);
    hi = __uint_as_float(b);
}

// theta [H, H+V] row-major -> packed chunk layout
__global__ void transpose_kernel(const float* __restrict__ theta) {
    int idx = blockIdx.x * blockDim.x + threadIdx.x;
    if (idx >= HV * Hh) return;
    int k = idx >> 8;
    int h = idx & 255;
    g_thetaT4[(k >> 2) * (Hh * 4) + h * 4 + (k & 3)] = theta[h * HV + k];
}

// Persistent kernel: each block owns BM batch rows for ALL T steps.
// Thread layout: hb = tid & 127 -> cols (hb, hb+128); r0 = (tid>>7)*8 -> rows r0..r0+7.
__global__ void __launch_bounds__(NTHR, 1) rnn_persistent(
    const float* __restrict__ sf,        // [B, T, V]
    const float* __restrict__ bias_g,    // [1]
    const float* __restrict__ theta_dot, // [1, H]
    float* __restrict__ out)             // [B]
{
    __shared__ __align__(16) float st_p[HV][BMP];   // state+token, k-major: 25.6 KB
    __shared__ __align__(16) float z_s[BM][Hh];     // z scratch: 16 KB
    __shared__ float mean_s[BM];
    __shared__ float rstd_s[BM];

    const int tid  = threadIdx.x;
    const int hb   = tid & 127;          // column base (cols hb, hb+128)
    const int r0   = (tid >> 7) * 8;     // row group: rows r0..r0+7
    const int wid  = tid >> 5, lane = tid & 31;
    const int b0   = blockIdx.x * BM;

    // token-load mapping: thread -> (row m_t, float4 group v4)
    const int m_t = tid >> 4;            // 0..15
    const int v4  = (tid & 15) * 4;      // 0,4,..,60

    const float bval = bias_g[0];
    const float td0 = theta_dot[hb];
    const float td1 = theta_dot[hb + 128];

    // ---- zero initial state ----
    for (int idx = tid; idx < HV * BMP; idx += NTHR)
        (&st_p[0][0])[idx] = 0.0f;

    // ---- stage tokens for t=0 ----
    {
        float4 tk = *reinterpret_cast<const float4*>(
            &sf[((size_t)(b0 + m_t) * Tt + 0) * Vv + v4]);
        st_p[Hh + v4 + 0][m_t] = tk.x;
        st_p[Hh + v4 + 1][m_t] = tk.y;
        st_p[Hh + v4 + 2][m_t] = tk.z;
        st_p[Hh + v4 + 3][m_t] = tk.w;
    }

    const float4* th0 = reinterpret_cast<const float4*>(g_thetaT4) + hb;
    const float4* th1 = th0 + 128;

    float zr[16];   // [col(2)][row(8)]

    for (int t = 0; t < Tt; t++) {
        __syncthreads();   // (d) state + token writes visible

        // prefetch next token (overlaps GEMM)
        float4 tok;
        const bool havet = (t + 1 < Tt);
        if (havet) {
            tok = *reinterpret_cast<const float4*>(
                &sf[((size_t)(b0 + m_t) * Tt + (t + 1)) * Vv + v4]);
        }

        // ---------- GEMM: 2 cols x 8 rows per thread ----------
        unsigned long long acc[8];   // [col(2)][rowpair(4)]
#pragma unroll
        for (int j = 0; j < 8; j++) acc[j] = pack2(bval);

        // theta software pipeline, depth 2
        float4 a0c = th0[0],       a1c = th1[0];
        float4 a0n = th0[Hh],      a1n = th1[Hh];

#pragma unroll 4
        for (int c = 0; c < NC; c++) {
            // prefetch theta chunk c+2 (covers L2 latency ~250 cyc)
            int cf = (c + 2 < NC) ? c + 2 : c;
            float4 a0f = th0[cf * Hh];
            float4 a1f = th1[cf * Hh];

            // batch all st loads for this chunk (MLP=8 LDS.128)
            ulonglong2 s[8];
#pragma unroll
            for (int kk = 0; kk < 4; kk++) {
                s[2 * kk]     = *reinterpret_cast<const ulonglong2*>(
                    &st_p[c * 4 + kk][r0]);          // rows r0..r0+3
                s[2 * kk + 1] = *reinterpret_cast<const ulonglong2*>(
                    &st_p[c * 4 + kk][r0 + 4]);      // rows r0+4..r0+7
            }

            float t0a[4], t1a[4];
            *reinterpret_cast<float4*>(t0a) = a0c;
            *reinterpret_cast<float4*>(t1a) = a1c;
#pragma unroll
            for (int kk = 0; kk < 4; kk++) {
                unsigned long long p0 = pack2(t0a[kk]);
                unsigned long long p1 = pack2(t1a[kk]);
                ulonglong2 sA = s[2 * kk];
                ulonglong2 sB = s[2 * kk + 1];
                acc[0] = fma2(sA.x, p0, acc[0]);
                acc[1] = fma2(sA.y, p0, acc[1]);
                acc[2] = fma2(sB.x, p0, acc[2]);
                acc[3] = fma2(sB.y, p0, acc[3]);
                acc[4] = fma2(sA.x, p1, acc[4]);
                acc[5] = fma2(sA.y, p1, acc[5]);
                acc[6] = fma2(sB.x, p1, acc[6]);
                acc[7] = fma2(sB.y, p1, acc[7]);
            }

            a0c = a0n; a1c = a1n;
            a0n = a0f; a1n = a1f;
        }

        // unpack z, stage into z_s
#pragma unroll
        for (int j = 0; j < 8; j++) unpack2(acc[j], zr[2 * j], zr[2 * j + 1]);
#pragma unroll
        for (int rr = 0; rr < 8; rr++) {
            z_s[r0 + rr][hb]       = zr[rr];        // col hb
            z_s[r0 + rr][hb + 128] = zr[8 + rr];    // col hb+128
        }

        __syncthreads();   // (b) z_s ready; st_p GEMM reads done

        // ---------- per-row mean / Bessel std: 8 warps x 2 rows ----------
        for (int m = wid; m < BM; m += 8) {
            float s = 0.0f, ss = 0.0f;
#pragma unroll
            for (int j = 0; j < Hh / 32; j++) {
                float v = z_s[m][j * 32 + lane];
                s += v;
                ss = fmaf(v, v, ss);
            }
#pragma unroll
            for (int off = 16; off; off >>= 1) {
                s  += __shfl_xor_sync(0xffffffffu, s, off);
                ss += __shfl_xor_sync(0xffffffffu, ss, off);
            }
            if (lane == 0) {
                float mean = s * (1.0f / Hh);
                float var  = (ss - (float)Hh * mean * mean) * (1.0f / (Hh - 1));
                var = fmaxf(var, 1e-30f);
                float r = rsqrtf(var);
                r = r * (1.5f - 0.5f * var * r * r);   // Newton refine
                mean_s[m] = mean;
                rstd_s[m] = r;
            }
        }

        // stage next tokens (st_p token rows free after bar (b))
        if (havet) {
            st_p[Hh + v4 + 0][m_t] = tok.x;
            st_p[Hh + v4 + 1][m_t] = tok.y;
            st_p[Hh + v4 + 2][m_t] = tok.z;
            st_p[Hh + v4 + 3][m_t] = tok.w;
        }

        __syncthreads();   // (c) mean/rstd ready

        // ---------- layernorm apply + relu, write state (vectorized STS.128) ----------
        {
            float mn[8], rs[8];
#pragma unroll
            for (int rr = 0; rr < 8; rr++) { mn[rr] = mean_s[r0 + rr]; rs[rr] = rstd_s[r0 + rr]; }
#pragma unroll
            for (int rr = 0; rr < 8; rr++) {
                zr[rr]     = fmaxf((zr[rr]     - mn[rr]) * rs[rr], 0.0f);
                zr[8 + rr] = fmaxf((zr[8 + rr] - mn[rr]) * rs[rr], 0.0f);
            }
            *reinterpret_cast<float4*>(&st_p[hb][r0])           = make_float4(zr[0], zr[1], zr[2], zr[3]);
            *reinterpret_cast<float4*>(&st_p[hb][r0 + 4])       = make_float4(zr[4], zr[5], zr[6], zr[7]);
            *reinterpret_cast<float4*>(&st_p[hb + 128][r0])     = make_float4(zr[8], zr[9], zr[10], zr[11]);
            *reinterpret_cast<float4*>(&st_p[hb + 128][r0 + 4]) = make_float4(zr[12], zr[13], zr[14], zr[15]);
        }
    }

    // ---------- logits: out[b] = sigmoid(sum_h state[b,h] * theta_dot[h]) ----------
#pragma unroll
    for (int rr = 0; rr < 8; rr++) {
        z_s[r0 + rr][hb]       = zr[rr]     * td0;
        z_s[r0 + rr][hb + 128] = zr[8 + rr] * td1;
    }
    __syncthreads();

    for (int m = wid; m < BM; m += 8) {
        float s = 0.0f;
#pragma unroll
        for (int j = 0; j < Hh / 32; j++) s += z_s[m][j * 32 + lane];
#pragma unroll
        for (int off = 16; off; off >>= 1)
            s += __shfl_xor_sync(0xffffffffu, s, off);
        if (lane == 0) out[b0 + m] = 1.0f / (1.0f + expf(-s));
    }
}

extern "C" void kernel_launch(void* const* d_in, const int* in_sizes, int n_in,
                              void* d_out, int out_size) {
    const float* sf        = (const float*)d_in[0];
    const float* theta     = (const float*)d_in[1];
    const float* bias      = (const float*)d_in[2];
    const float* theta_dot = (const float*)d_in[3];
    float*       out       = (float*)d_out;

    transpose_kernel<<<HV, 256>>>(theta);
    rnn_persistent<<<NBLK, NTHR>>>(sf, bias, theta_dot, out);
}